// round 4
// baseline (speedup 1.0000x reference)
#include <cuda_runtime.h>
#include <math.h>

#define B_    128
#define PAST_ 256
#define FUT_  128
#define D_    128
#define RU_   512
#define LD_   128
#define FCN_  512
#define TL_   128
#define HDEC_ 640
#define G3RU  1536
#define G3HD  1920

// ---------------- static device scratch (no allocations anywhere) ----------
__device__ float g_gi_phi[(size_t)B_ * PAST_ * G3RU];   // 201 MB
__device__ float g_gi_xr [(size_t)B_ * FUT_  * G3RU];   // 100 MB
__device__ float g_h_phi [B_ * RU_];
__device__ float g_h_xr  [B_ * RU_];
__device__ float g_feat  [B_ * 2 * RU_];
__device__ float g_ghp   [2 * 4 * B_ * G3RU];           // enc gh partials [g][s][B][G3RU]
__device__ float g_m1p   [2 * 8 * B_ * 512];            // [(br*8+s)][B][512]
__device__ float g_m2p   [2 * 4 * B_ * 256];
__device__ float g_m3p   [2 * 2 * B_ * 128];
__device__ float g_hdec  [B_ * HDEC_];
__device__ float g_xdec  [B_ * D_];
__device__ float g_dghp  [6 * B_ * G3HD];               // dec: s=0 Gi, s=1..5 Gh splits
__device__ float g_fcp   [5 * B_ * FCN_];
__device__ float g_outp  [4 * B_ * D_];
__device__ unsigned g_barcnt;
__device__ unsigned g_bargen;

// ---------------- grid-wide barrier (all blocks co-resident) ---------------
__device__ __forceinline__ void gridbar() {
    __syncthreads();
    if (threadIdx.x == 0) {
        unsigned my = *(volatile unsigned*)&g_bargen;
        __threadfence();
        unsigned t = atomicAdd(&g_barcnt, 1u);
        if (t == gridDim.x - 1) {
            g_barcnt = 0;
            __threadfence();
            atomicAdd(&g_bargen, 1u);
        } else {
            while (*(volatile unsigned*)&g_bargen == my) { }
        }
        __threadfence();
    }
    __syncthreads();
}

__device__ __forceinline__ float actf(float v, int act) {
    if (act == 1) return v > 0.f ? v : 0.01f * v;   // leaky_relu
    if (act == 2) return fmaxf(v, 0.f);             // relu
    return v;
}
__device__ __forceinline__ float sigm(float x) { return 1.f / (1.f + expf(-x)); }

// ---------------- 32x64 tile GEMM, K-chunk = 128 (4 sub-chunks of 32) ------
// C[m0..+32, n0..+64] = A[:, k0..k0+128] @ W[:, k0..k0+128]^T (+ bias if addBias)
// A-loader optionally reduces nred partials (stride partStride) with actIn.
struct Smem {
    float As[32][36];
    float Ws[32][68];
};

__device__ __noinline__ void tile_gemm(
    Smem* sm,
    const float* __restrict__ A, int ldA, size_t partStride, int nred, int actIn,
    const float* __restrict__ W, int ldW,
    const float* __restrict__ bias, int addBias,
    float* __restrict__ C, int ldC,
    int m0, int n0, int k0)
{
    const int tid = threadIdx.x;
    const int tx = tid & 15, ty = tid >> 4;
    float acc[4][4];
#pragma unroll
    for (int i = 0; i < 4; i++)
#pragma unroll
        for (int j = 0; j < 4; j++) acc[i][j] = 0.f;

#pragma unroll 1
    for (int kc = 0; kc < 4; kc++) {
        const int kb = k0 + kc * 32;
        // A tile: 32 rows x 32 cols
#pragma unroll
        for (int i = 0; i < 8; i++) {
            int e = tid + i * 128;
            int r = e >> 5, c = e & 31;
            const float* ap = A + (size_t)(m0 + r) * ldA + kb + c;
            float v;
            if (nred == 1) {
                v = __ldcg(ap);
            } else {
                v = 0.f;
                for (int p = 0; p < nred; p++) v += __ldcg(ap + (size_t)p * partStride);
                v = actf(v, actIn);
            }
            sm->As[c][r] = v;
        }
        // W tile: 64 rows x 32 cols
#pragma unroll
        for (int i = 0; i < 16; i++) {
            int e = tid + i * 128;
            int r = e >> 5, c = e & 31;
            sm->Ws[c][r] = __ldg(W + (size_t)(n0 + r) * ldW + kb + c);
        }
        __syncthreads();
#pragma unroll
        for (int kk = 0; kk < 32; kk++) {
            float4 av = *(const float4*)&sm->As[kk][ty * 4];
            float4 wv = *(const float4*)&sm->Ws[kk][tx * 4];
            float a[4] = {av.x, av.y, av.z, av.w};
            float w[4] = {wv.x, wv.y, wv.z, wv.w};
#pragma unroll
            for (int i = 0; i < 4; i++)
#pragma unroll
                for (int j = 0; j < 4; j++) acc[i][j] = fmaf(a[i], w[j], acc[i][j]);
        }
        __syncthreads();
    }

#pragma unroll
    for (int i = 0; i < 4; i++) {
        int m = m0 + ty * 4 + i;
#pragma unroll
        for (int j = 0; j < 4; j++) {
            int n = n0 + tx * 4 + j;
            float v = acc[i][j] + (addBias ? __ldg(bias + n) : 0.f);
            __stcg(C + (size_t)m * ldC + n, v);
        }
    }
}

// ---------------- persistent kernel ---------------------------------------
__global__ void __launch_bounds__(128, 4) vae_persistent(
    const float* __restrict__ past, const float* __restrict__ future,
    const float* __restrict__ eps,
    const float* __restrict__ phi_Wih, const float* __restrict__ phi_Whh,
    const float* __restrict__ phi_bih, const float* __restrict__ phi_bhh,
    const float* __restrict__ xr_Wih,  const float* __restrict__ xr_Whh,
    const float* __restrict__ xr_bih,  const float* __restrict__ xr_bhh,
    const float* __restrict__ mu_W1, const float* __restrict__ mu_b1,
    const float* __restrict__ mu_W2, const float* __restrict__ mu_b2,
    const float* __restrict__ mu_W3, const float* __restrict__ mu_b3,
    const float* __restrict__ lv_W1, const float* __restrict__ lv_b1,
    const float* __restrict__ lv_W2, const float* __restrict__ lv_b2,
    const float* __restrict__ lv_W3, const float* __restrict__ lv_b3,
    const float* __restrict__ dec_Wih, const float* __restrict__ dec_Whh,
    const float* __restrict__ dec_bih, const float* __restrict__ dec_bhh,
    const float* __restrict__ fc_W, const float* __restrict__ fc_b,
    const float* __restrict__ out_W, const float* __restrict__ out_b,
    float* __restrict__ x_mu, float* __restrict__ z_mu_o, float* __restrict__ z_lv_o)
{
    __shared__ Smem sm;
    const int nblk = gridDim.x;
    const int bid  = blockIdx.x;
    const int tid  = threadIdx.x;
    const int gtid = bid * 128 + tid;
    const int nthr = nblk * 128;

    // ---------- P0: time-parallel input projections + zero hidden ----------
    {
        const int T1 = (B_ * PAST_ / 32) * (G3RU / 64);   // 24576
        const int T2 = (B_ * FUT_  / 32) * (G3RU / 64);   // 12288
#pragma unroll 1
        for (int tl = bid; tl < T1 + T2; tl += nblk) {
            if (tl < T1) {
                int m0 = (tl / 24) * 32, n0 = (tl % 24) * 64;
                tile_gemm(&sm, past, D_, 0, 1, 0, phi_Wih, D_, phi_bih, 1,
                          g_gi_phi, G3RU, m0, n0, 0);
            } else {
                int r = tl - T1;
                int m0 = (r / 24) * 32, n0 = (r % 24) * 64;
                tile_gemm(&sm, future, D_, 0, 1, 0, xr_Wih, D_, xr_bih, 1,
                          g_gi_xr, G3RU, m0, n0, 0);
            }
        }
        for (int i = gtid; i < 2 * B_ * RU_; i += nthr) {
            if (i < B_ * RU_) __stcg(&g_h_phi[i], 0.f);
            else              __stcg(&g_h_xr[i - B_ * RU_], 0.f);
        }
    }
    gridbar();

    // ---------- encoder recurrences ----------
#pragma unroll 1
    for (int t = 0; t < PAST_; t++) {
        const int ngru = (t < FUT_) ? 2 : 1;
        const int TT = 4 * 24 * 4;   // tiles per GRU (m x n x ksplit)
#pragma unroll 1
        for (int tl = bid; tl < ngru * TT; tl += nblk) {
            int g = tl / TT, r = tl % TT;
            int s = r & 3; r >>= 2;
            int n0 = (r % 24) * 64, m0 = (r / 24) * 32;
            const float* A  = g ? g_h_xr : g_h_phi;
            const float* W  = g ? xr_Whh : phi_Whh;
            const float* bb = g ? xr_bhh : phi_bhh;
            float* C = g_ghp + ((size_t)g * 4 + s) * (B_ * G3RU);
            tile_gemm(&sm, A, RU_, 0, 1, 0, W, RU_, bb, s == 0, C, G3RU, m0, n0, s * 128);
        }
        gridbar();
        for (int i = gtid; i < ngru * B_ * RU_; i += nthr) {
            int g = i / (B_ * RU_), r = i % (B_ * RU_);
            int m = r / RU_, j = r % RU_;
            float sr = 0.f, sz = 0.f, sn = 0.f;
#pragma unroll
            for (int s = 0; s < 4; s++) {
                const float* gp = g_ghp + ((size_t)g * 4 + s) * (B_ * G3RU) + (size_t)m * G3RU;
                sr += __ldcg(gp + j);
                sz += __ldcg(gp + RU_ + j);
                sn += __ldcg(gp + 2 * RU_ + j);
            }
            const float* gim = g ? (g_gi_xr  + ((size_t)m * FUT_  + t) * G3RU)
                                 : (g_gi_phi + ((size_t)m * PAST_ + t) * G3RU);
            float rr = sigm(__ldcg(gim + j) + sr);
            float zz = sigm(__ldcg(gim + RU_ + j) + sz);
            float nn = tanhf(__ldcg(gim + 2 * RU_ + j) + rr * sn);
            float* hp = (g ? g_h_xr : g_h_phi) + (size_t)m * RU_ + j;
            float hv = __ldcg(hp);
            __stcg(hp, (1.f - zz) * nn + zz * hv);
        }
        gridbar();
    }

    // ---------- features ----------
    for (int i = gtid; i < B_ * 2 * RU_; i += nthr) {
        int m = i / (2 * RU_), c = i % (2 * RU_);
        float v = (c < RU_) ? __ldcg(&g_h_phi[m * RU_ + c]) : __ldcg(&g_h_xr[m * RU_ + c - RU_]);
        __stcg(&g_feat[i], v);
    }
    gridbar();

    // ---------- MLP L1: [B,512], K=1024 (S=8), both branches ----------
#pragma unroll 1
    for (int tl = bid; tl < 2 * 4 * 8 * 8; tl += nblk) {
        int br = tl / 256, r = tl % 256;
        int s = r & 7; r >>= 3;
        int n0 = (r % 8) * 64, m0 = (r / 8) * 32;
        const float* W = br ? lv_W1 : mu_W1;
        const float* bb = br ? lv_b1 : mu_b1;
        float* C = g_m1p + ((size_t)br * 8 + s) * (B_ * 512);
        tile_gemm(&sm, g_feat, 2 * RU_, 0, 1, 0, W, 2 * RU_, bb, s == 0, C, 512, m0, n0, s * 128);
    }
    gridbar();
    // ---------- MLP L2: [B,256], K=512 (S=4); A = leaky(sum8 L1 partials) ----
#pragma unroll 1
    for (int tl = bid; tl < 2 * 4 * 4 * 4; tl += nblk) {
        int br = tl / 64, r = tl % 64;
        int s = r & 3; r >>= 2;
        int n0 = (r % 4) * 64, m0 = (r / 4) * 32;
        const float* W = br ? lv_W2 : mu_W2;
        const float* bb = br ? lv_b2 : mu_b2;
        const float* A = g_m1p + (size_t)br * 8 * (B_ * 512);
        float* C = g_m2p + ((size_t)br * 4 + s) * (B_ * 256);
        tile_gemm(&sm, A, 512, (size_t)B_ * 512, 8, 1, W, 512, bb, s == 0, C, 256, m0, n0, s * 128);
    }
    gridbar();
    // ---------- MLP L3: [B,128], K=256 (S=2); A = leaky(sum4 L2 partials) ----
#pragma unroll 1
    for (int tl = bid; tl < 2 * 4 * 2 * 2; tl += nblk) {
        int br = tl / 16, r = tl % 16;
        int s = r & 1; r >>= 1;
        int n0 = (r % 2) * 64, m0 = (r / 2) * 32;
        const float* W = br ? lv_W3 : mu_W3;
        const float* bb = br ? lv_b3 : mu_b3;
        const float* A = g_m2p + (size_t)br * 4 * (B_ * 256);
        float* C = g_m3p + ((size_t)br * 2 + s) * (B_ * 128);
        tile_gemm(&sm, A, 256, (size_t)B_ * 256, 4, 1, W, 256, bb, s == 0, C, 128, m0, n0, s * 128);
    }
    gridbar();

    // ---------- prep decoder: z, h_dec, x_dec; emit z_mu / z_logvar --------
    for (int i = gtid; i < B_ * (HDEC_ + D_); i += nthr) {
        int m = i / (HDEC_ + D_), c = i % (HDEC_ + D_);
        if (c < RU_) {
            __stcg(&g_hdec[m * HDEC_ + c], __ldcg(&g_h_phi[m * RU_ + c]));
        } else if (c < HDEC_) {
            int l = c - RU_;
            float zm = __ldcg(&g_m3p[(size_t)(0) * B_ * 128 + m * 128 + l])
                     + __ldcg(&g_m3p[(size_t)(1) * B_ * 128 + m * 128 + l]);
            float zl = __ldcg(&g_m3p[(size_t)(2) * B_ * 128 + m * 128 + l])
                     + __ldcg(&g_m3p[(size_t)(3) * B_ * 128 + m * 128 + l]);
            z_mu_o[m * LD_ + l] = zm;
            z_lv_o[m * LD_ + l] = zl;
            float z = zm + __ldg(&eps[m * LD_ + l]) * expf(0.5f * zl);
            __stcg(&g_hdec[m * HDEC_ + c], z);
        } else {
            int d = c - HDEC_;
            __stcg(&g_xdec[m * D_ + d], __ldg(&past[((size_t)m * PAST_ + PAST_ - 1) * D_ + d]));
        }
    }
    gridbar();

    // ---------- decoder recurrence ----------
#pragma unroll 1
    for (int t = 0; t < TL_; t++) {
        // D1: gate partials. s=0: Gi (K=128); s=1..5: Gh splits (K=640)
#pragma unroll 1
        for (int tl = bid; tl < 4 * 30 * 6; tl += nblk) {
            int s = tl % 6, r = tl / 6;
            int n0 = (r % 30) * 64, m0 = (r / 30) * 32;
            float* C = g_dghp + (size_t)s * (B_ * G3HD);
            if (s == 0)
                tile_gemm(&sm, g_xdec, D_, 0, 1, 0, dec_Wih, D_, dec_bih, 1, C, G3HD, m0, n0, 0);
            else
                tile_gemm(&sm, g_hdec, HDEC_, 0, 1, 0, dec_Whh, HDEC_, dec_bhh, s == 1,
                          C, G3HD, m0, n0, (s - 1) * 128);
        }
        gridbar();
        // D2: GRU pointwise (Gi separate from Gh for the n-gate)
        for (int i = gtid; i < B_ * HDEC_; i += nthr) {
            int m = i / HDEC_, j = i % HDEC_;
            const float* g0 = g_dghp + (size_t)m * G3HD;
            float ir = __ldcg(g0 + j), iz = __ldcg(g0 + HDEC_ + j), in = __ldcg(g0 + 2 * HDEC_ + j);
            float hr = 0.f, hz = 0.f, hn = 0.f;
#pragma unroll
            for (int s = 1; s < 6; s++) {
                const float* gp = g_dghp + (size_t)s * (B_ * G3HD) + (size_t)m * G3HD;
                hr += __ldcg(gp + j);
                hz += __ldcg(gp + HDEC_ + j);
                hn += __ldcg(gp + 2 * HDEC_ + j);
            }
            float rr = sigm(ir + hr);
            float zz = sigm(iz + hz);
            float nn = tanhf(in + rr * hn);
            float* hp = &g_hdec[(size_t)m * HDEC_ + j];
            float hv = __ldcg(hp);
            __stcg(hp, (1.f - zz) * nn + zz * hv);
        }
        gridbar();
        // D3: fc partials [B,512], K=640 (S=5)
#pragma unroll 1
        for (int tl = bid; tl < 4 * 8 * 5; tl += nblk) {
            int s = tl % 5, r = tl / 5;
            int n0 = (r % 8) * 64, m0 = (r / 8) * 32;
            float* C = g_fcp + (size_t)s * (B_ * FCN_);
            tile_gemm(&sm, g_hdec, HDEC_, 0, 1, 0, fc_W, HDEC_, fc_b, s == 0, C, FCN_, m0, n0, s * 128);
        }
        gridbar();
        // D4: out partials [B,128], K=512 (S=4); A = relu(sum5 fc partials)
#pragma unroll 1
        for (int tl = bid; tl < 4 * 2 * 4; tl += nblk) {
            int s = tl % 4, r = tl / 4;
            int n0 = (r % 2) * 64, m0 = (r / 2) * 32;
            float* C = g_outp + (size_t)s * (B_ * D_);
            tile_gemm(&sm, g_fcp, FCN_, (size_t)B_ * FCN_, 5, 2, out_W, FCN_, out_b, s == 0,
                      C, D_, m0, n0, s * 128);
        }
        gridbar();
        // D5: reduce -> x_mu[:, t, :] and feedback x_dec
        for (int i = gtid; i < B_ * D_; i += nthr) {
            int m = i / D_, d = i % D_;
            float v = 0.f;
#pragma unroll
            for (int s = 0; s < 4; s++) v += __ldcg(&g_outp[(size_t)s * B_ * D_ + m * D_ + d]);
            x_mu[((size_t)m * TL_ + t) * D_ + d] = v;
            __stcg(&g_xdec[m * D_ + d], v);
        }
        gridbar();
    }
}

// ---------------- host launch: single graph node ---------------------------
extern "C" void kernel_launch(void* const* d_in, const int* in_sizes, int n_in,
                              void* d_out, int out_size)
{
    (void)in_sizes; (void)n_in; (void)out_size;
    const float* past    = (const float*)d_in[0];
    const float* future  = (const float*)d_in[1];
    const float* eps     = (const float*)d_in[2];
    const float* phi_Wih = (const float*)d_in[3];
    const float* phi_Whh = (const float*)d_in[4];
    const float* phi_bih = (const float*)d_in[5];
    const float* phi_bhh = (const float*)d_in[6];
    const float* xr_Wih  = (const float*)d_in[7];
    const float* xr_Whh  = (const float*)d_in[8];
    const float* xr_bih  = (const float*)d_in[9];
    const float* xr_bhh  = (const float*)d_in[10];
    const float* mu_W1   = (const float*)d_in[11];
    const float* mu_b1   = (const float*)d_in[12];
    const float* mu_W2   = (const float*)d_in[13];
    const float* mu_b2   = (const float*)d_in[14];
    const float* mu_W3   = (const float*)d_in[15];
    const float* mu_b3   = (const float*)d_in[16];
    const float* lv_W1   = (const float*)d_in[17];
    const float* lv_b1   = (const float*)d_in[18];
    const float* lv_W2   = (const float*)d_in[19];
    const float* lv_b2   = (const float*)d_in[20];
    const float* lv_W3   = (const float*)d_in[21];
    const float* lv_b3   = (const float*)d_in[22];
    const float* dec_Wih = (const float*)d_in[23];
    const float* dec_Whh = (const float*)d_in[24];
    const float* dec_bih = (const float*)d_in[25];
    const float* dec_bhh = (const float*)d_in[26];
    const float* fc_W    = (const float*)d_in[27];
    const float* fc_b    = (const float*)d_in[28];
    const float* out_W   = (const float*)d_in[29];
    const float* out_b   = (const float*)d_in[30];

    float* outp = (float*)d_out;
    float* x_mu = outp;
    float* z_mu = outp + (size_t)B_ * TL_ * D_;
    float* z_lv = z_mu + (size_t)B_ * LD_;

    int dev = 0, sms = 148;
    cudaGetDevice(&dev);
    cudaDeviceGetAttribute(&sms, cudaDevAttrMultiProcessorCount, dev);
    int nblk = sms * 4;

    vae_persistent<<<nblk, 128>>>(
        past, future, eps,
        phi_Wih, phi_Whh, phi_bih, phi_bhh,
        xr_Wih, xr_Whh, xr_bih, xr_bhh,
        mu_W1, mu_b1, mu_W2, mu_b2, mu_W3, mu_b3,
        lv_W1, lv_b1, lv_W2, lv_b2, lv_W3, lv_b3,
        dec_Wih, dec_Whh, dec_bih, dec_bhh,
        fc_W, fc_b, out_W, out_b,
        x_mu, z_mu, z_lv);
}

// round 5
// speedup vs baseline: 1.0305x; 1.0305x over previous
#include <cuda_runtime.h>
#include <math.h>

#define B_    128
#define PAST_ 256
#define FUT_  128
#define D_    128
#define RU_   512
#define LD_   128
#define FCN_  512
#define TL_   128
#define HDEC_ 640
#define G3RU  1536
#define G3HD  1920

// ---------------- static device scratch (no allocations anywhere) ----------
__device__ float g_gi_phi[(size_t)B_ * PAST_ * G3RU];   // 201 MB
__device__ float g_gi_xr [(size_t)B_ * FUT_  * G3RU];   // 100 MB
__device__ float g_h_phi [B_ * RU_];
__device__ float g_h_xr  [B_ * RU_];
__device__ float g_feat  [B_ * 2 * RU_];
__device__ float g_ghp   [2 * 4 * B_ * G3RU];           // enc gh partials [g][s][B][G3RU]
__device__ float g_m1p   [2 * 8 * B_ * 512];            // [(br*8+s)][B][512]
__device__ float g_m2p   [2 * 4 * B_ * 256];
__device__ float g_m3p   [2 * 2 * B_ * 128];
__device__ float g_hdec  [B_ * HDEC_];
__device__ float g_xdec  [B_ * D_];
__device__ float g_dghp  [6 * B_ * G3HD];               // dec: s=0 Gi, s=1..5 Gh splits
__device__ float g_fcp   [5 * B_ * FCN_];
__device__ float g_outp  [4 * B_ * D_];
__device__ unsigned g_barcnt;
__device__ unsigned g_bargen;

// ---------------- grid-wide barrier (all blocks co-resident) ---------------
__device__ __forceinline__ void gridbar() {
    __syncthreads();
    if (threadIdx.x == 0) {
        unsigned my = *(volatile unsigned*)&g_bargen;
        __threadfence();
        unsigned t = atomicAdd(&g_barcnt, 1u);
        if (t == gridDim.x - 1) {
            g_barcnt = 0;
            __threadfence();
            atomicAdd(&g_bargen, 1u);
        } else {
            while (*(volatile unsigned*)&g_bargen == my) { }
        }
        __threadfence();
    }
    __syncthreads();
}

__device__ __forceinline__ float actf(float v, int act) {
    if (act == 1) return v > 0.f ? v : 0.01f * v;   // leaky_relu
    if (act == 2) return fmaxf(v, 0.f);             // relu
    return v;
}
__device__ __forceinline__ float sigm(float x) { return 1.f / (1.f + expf(-x)); }

// ---------------- 32x64 tile GEMM, K-chunk = 128 (4 sub-chunks of 32) ------
// C[m0..+32, n0..+64] = A[:, k0..k0+128] @ W[:, k0..k0+128]^T (+ bias if addBias)
// A-loader optionally reduces nred partials (stride partStride) with actIn.
struct Smem {
    float As[32][36];
    float Ws[32][68];
};

__device__ __noinline__ void tile_gemm(
    Smem* sm,
    const float* __restrict__ A, int ldA, size_t partStride, int nred, int actIn,
    const float* __restrict__ W, int ldW,
    const float* __restrict__ bias, int addBias,
    float* __restrict__ C, int ldC,
    int m0, int n0, int k0)
{
    const int tid = threadIdx.x;
    const int tx = tid & 15, ty = tid >> 4;
    float acc[4][4];
#pragma unroll
    for (int i = 0; i < 4; i++)
#pragma unroll
        for (int j = 0; j < 4; j++) acc[i][j] = 0.f;

#pragma unroll 1
    for (int kc = 0; kc < 4; kc++) {
        const int kb = k0 + kc * 32;
        // A tile: 32 rows x 32 cols
#pragma unroll
        for (int i = 0; i < 8; i++) {
            int e = tid + i * 128;
            int r = e >> 5, c = e & 31;
            const float* ap = A + (size_t)(m0 + r) * ldA + kb + c;
            float v;
            if (nred == 1) {
                v = __ldcg(ap);
            } else {
                v = 0.f;
                for (int p = 0; p < nred; p++) v += __ldcg(ap + (size_t)p * partStride);
                v = actf(v, actIn);
            }
            sm->As[c][r] = v;
        }
        // W tile: 64 rows x 32 cols
#pragma unroll
        for (int i = 0; i < 16; i++) {
            int e = tid + i * 128;
            int r = e >> 5, c = e & 31;
            sm->Ws[c][r] = __ldg(W + (size_t)(n0 + r) * ldW + kb + c);
        }
        __syncthreads();
#pragma unroll
        for (int kk = 0; kk < 32; kk++) {
            float4 av = *(const float4*)&sm->As[kk][ty * 4];
            float4 wv = *(const float4*)&sm->Ws[kk][tx * 4];
            float a[4] = {av.x, av.y, av.z, av.w};
            float w[4] = {wv.x, wv.y, wv.z, wv.w};
#pragma unroll
            for (int i = 0; i < 4; i++)
#pragma unroll
                for (int j = 0; j < 4; j++) acc[i][j] = fmaf(a[i], w[j], acc[i][j]);
        }
        __syncthreads();
    }

#pragma unroll
    for (int i = 0; i < 4; i++) {
        int m = m0 + ty * 4 + i;
#pragma unroll
        for (int j = 0; j < 4; j++) {
            int n = n0 + tx * 4 + j;
            float v = acc[i][j] + (addBias ? __ldg(bias + n) : 0.f);
            __stcg(C + (size_t)m * ldC + n, v);
        }
    }
}

// ---------------- persistent kernel ---------------------------------------
__global__ void __launch_bounds__(128, 4) vae_persistent(
    const float* __restrict__ past, const float* __restrict__ future,
    const float* __restrict__ eps,
    const float* __restrict__ phi_Wih, const float* __restrict__ phi_Whh,
    const float* __restrict__ phi_bih, const float* __restrict__ phi_bhh,
    const float* __restrict__ xr_Wih,  const float* __restrict__ xr_Whh,
    const float* __restrict__ xr_bih,  const float* __restrict__ xr_bhh,
    const float* __restrict__ mu_W1, const float* __restrict__ mu_b1,
    const float* __restrict__ mu_W2, const float* __restrict__ mu_b2,
    const float* __restrict__ mu_W3, const float* __restrict__ mu_b3,
    const float* __restrict__ lv_W1, const float* __restrict__ lv_b1,
    const float* __restrict__ lv_W2, const float* __restrict__ lv_b2,
    const float* __restrict__ lv_W3, const float* __restrict__ lv_b3,
    const float* __restrict__ dec_Wih, const float* __restrict__ dec_Whh,
    const float* __restrict__ dec_bih, const float* __restrict__ dec_bhh,
    const float* __restrict__ fc_W, const float* __restrict__ fc_b,
    const float* __restrict__ out_W, const float* __restrict__ out_b,
    float* __restrict__ x_mu, float* __restrict__ z_mu_o, float* __restrict__ z_lv_o)
{
    __shared__ Smem sm;
    const int nblk = gridDim.x;
    const int bid  = blockIdx.x;
    const int tid  = threadIdx.x;
    const int gtid = bid * 128 + tid;
    const int nthr = nblk * 128;

    // ---------- P0: time-parallel input projections + zero hidden ----------
    {
        const int T1 = (B_ * PAST_ / 32) * (G3RU / 64);   // 24576
        const int T2 = (B_ * FUT_  / 32) * (G3RU / 64);   // 12288
#pragma unroll 1
        for (int tl = bid; tl < T1 + T2; tl += nblk) {
            if (tl < T1) {
                int m0 = (tl / 24) * 32, n0 = (tl % 24) * 64;
                tile_gemm(&sm, past, D_, 0, 1, 0, phi_Wih, D_, phi_bih, 1,
                          g_gi_phi, G3RU, m0, n0, 0);
            } else {
                int r = tl - T1;
                int m0 = (r / 24) * 32, n0 = (r % 24) * 64;
                tile_gemm(&sm, future, D_, 0, 1, 0, xr_Wih, D_, xr_bih, 1,
                          g_gi_xr, G3RU, m0, n0, 0);
            }
        }
        for (int i = gtid; i < 2 * B_ * RU_; i += nthr) {
            if (i < B_ * RU_) __stcg(&g_h_phi[i], 0.f);
            else              __stcg(&g_h_xr[i - B_ * RU_], 0.f);
        }
    }
    gridbar();

    // ---------- encoder recurrences ----------
#pragma unroll 1
    for (int t = 0; t < PAST_; t++) {
        const int ngru = (t < FUT_) ? 2 : 1;
        const int TT = 4 * 24 * 4;   // tiles per GRU (m x n x ksplit)
#pragma unroll 1
        for (int tl = bid; tl < ngru * TT; tl += nblk) {
            int g = tl / TT, r = tl % TT;
            int s = r & 3; r >>= 2;
            int n0 = (r % 24) * 64, m0 = (r / 24) * 32;
            const float* A  = g ? g_h_xr : g_h_phi;
            const float* W  = g ? xr_Whh : phi_Whh;
            const float* bb = g ? xr_bhh : phi_bhh;
            float* C = g_ghp + ((size_t)g * 4 + s) * (B_ * G3RU);
            tile_gemm(&sm, A, RU_, 0, 1, 0, W, RU_, bb, s == 0, C, G3RU, m0, n0, s * 128);
        }
        gridbar();
        for (int i = gtid; i < ngru * B_ * RU_; i += nthr) {
            int g = i / (B_ * RU_), r = i % (B_ * RU_);
            int m = r / RU_, j = r % RU_;
            float sr = 0.f, sz = 0.f, sn = 0.f;
#pragma unroll
            for (int s = 0; s < 4; s++) {
                const float* gp = g_ghp + ((size_t)g * 4 + s) * (B_ * G3RU) + (size_t)m * G3RU;
                sr += __ldcg(gp + j);
                sz += __ldcg(gp + RU_ + j);
                sn += __ldcg(gp + 2 * RU_ + j);
            }
            const float* gim = g ? (g_gi_xr  + ((size_t)m * FUT_  + t) * G3RU)
                                 : (g_gi_phi + ((size_t)m * PAST_ + t) * G3RU);
            float rr = sigm(__ldcg(gim + j) + sr);
            float zz = sigm(__ldcg(gim + RU_ + j) + sz);
            float nn = tanhf(__ldcg(gim + 2 * RU_ + j) + rr * sn);
            float* hp = (g ? g_h_xr : g_h_phi) + (size_t)m * RU_ + j;
            float hv = __ldcg(hp);
            __stcg(hp, (1.f - zz) * nn + zz * hv);
        }
        gridbar();
    }

    // ---------- features ----------
    for (int i = gtid; i < B_ * 2 * RU_; i += nthr) {
        int m = i / (2 * RU_), c = i % (2 * RU_);
        float v = (c < RU_) ? __ldcg(&g_h_phi[m * RU_ + c]) : __ldcg(&g_h_xr[m * RU_ + c - RU_]);
        __stcg(&g_feat[i], v);
    }
    gridbar();

    // ---------- MLP L1: [B,512], K=1024 (S=8), both branches ----------
#pragma unroll 1
    for (int tl = bid; tl < 2 * 4 * 8 * 8; tl += nblk) {
        int br = tl / 256, r = tl % 256;
        int s = r & 7; r >>= 3;
        int n0 = (r % 8) * 64, m0 = (r / 8) * 32;
        const float* W = br ? lv_W1 : mu_W1;
        const float* bb = br ? lv_b1 : mu_b1;
        float* C = g_m1p + ((size_t)br * 8 + s) * (B_ * 512);
        tile_gemm(&sm, g_feat, 2 * RU_, 0, 1, 0, W, 2 * RU_, bb, s == 0, C, 512, m0, n0, s * 128);
    }
    gridbar();
    // ---------- MLP L2: [B,256], K=512 (S=4); A = leaky(sum8 L1 partials) ----
#pragma unroll 1
    for (int tl = bid; tl < 2 * 4 * 4 * 4; tl += nblk) {
        int br = tl / 64, r = tl % 64;
        int s = r & 3; r >>= 2;
        int n0 = (r % 4) * 64, m0 = (r / 4) * 32;
        const float* W = br ? lv_W2 : mu_W2;
        const float* bb = br ? lv_b2 : mu_b2;
        const float* A = g_m1p + (size_t)br * 8 * (B_ * 512);
        float* C = g_m2p + ((size_t)br * 4 + s) * (B_ * 256);
        tile_gemm(&sm, A, 512, (size_t)B_ * 512, 8, 1, W, 512, bb, s == 0, C, 256, m0, n0, s * 128);
    }
    gridbar();
    // ---------- MLP L3: [B,128], K=256 (S=2); A = leaky(sum4 L2 partials) ----
#pragma unroll 1
    for (int tl = bid; tl < 2 * 4 * 2 * 2; tl += nblk) {
        int br = tl / 16, r = tl % 16;
        int s = r & 1; r >>= 1;
        int n0 = (r % 2) * 64, m0 = (r / 2) * 32;
        const float* W = br ? lv_W3 : mu_W3;
        const float* bb = br ? lv_b3 : mu_b3;
        const float* A = g_m2p + (size_t)br * 4 * (B_ * 256);
        float* C = g_m3p + ((size_t)br * 2 + s) * (B_ * 128);
        tile_gemm(&sm, A, 256, (size_t)B_ * 256, 4, 1, W, 256, bb, s == 0, C, 128, m0, n0, s * 128);
    }
    gridbar();

    // ---------- prep decoder: z, h_dec, x_dec; emit z_mu / z_logvar --------
    for (int i = gtid; i < B_ * (HDEC_ + D_); i += nthr) {
        int m = i / (HDEC_ + D_), c = i % (HDEC_ + D_);
        if (c < RU_) {
            __stcg(&g_hdec[m * HDEC_ + c], __ldcg(&g_h_phi[m * RU_ + c]));
        } else if (c < HDEC_) {
            int l = c - RU_;
            float zm = __ldcg(&g_m3p[(size_t)(0) * B_ * 128 + m * 128 + l])
                     + __ldcg(&g_m3p[(size_t)(1) * B_ * 128 + m * 128 + l]);
            float zl = __ldcg(&g_m3p[(size_t)(2) * B_ * 128 + m * 128 + l])
                     + __ldcg(&g_m3p[(size_t)(3) * B_ * 128 + m * 128 + l]);
            z_mu_o[m * LD_ + l] = zm;
            z_lv_o[m * LD_ + l] = zl;
            float z = zm + __ldg(&eps[m * LD_ + l]) * expf(0.5f * zl);
            __stcg(&g_hdec[m * HDEC_ + c], z);
        } else {
            int d = c - HDEC_;
            __stcg(&g_xdec[m * D_ + d], __ldg(&past[((size_t)m * PAST_ + PAST_ - 1) * D_ + d]));
        }
    }
    gridbar();

    // ---------- decoder recurrence ----------
#pragma unroll 1
    for (int t = 0; t < TL_; t++) {
        // D1: gate partials. s=0: Gi (K=128); s=1..5: Gh splits (K=640)
#pragma unroll 1
        for (int tl = bid; tl < 4 * 30 * 6; tl += nblk) {
            int s = tl % 6, r = tl / 6;
            int n0 = (r % 30) * 64, m0 = (r / 30) * 32;
            float* C = g_dghp + (size_t)s * (B_ * G3HD);
            if (s == 0)
                tile_gemm(&sm, g_xdec, D_, 0, 1, 0, dec_Wih, D_, dec_bih, 1, C, G3HD, m0, n0, 0);
            else
                tile_gemm(&sm, g_hdec, HDEC_, 0, 1, 0, dec_Whh, HDEC_, dec_bhh, s == 1,
                          C, G3HD, m0, n0, (s - 1) * 128);
        }
        gridbar();
        // D2: GRU pointwise (Gi separate from Gh for the n-gate)
        for (int i = gtid; i < B_ * HDEC_; i += nthr) {
            int m = i / HDEC_, j = i % HDEC_;
            const float* g0 = g_dghp + (size_t)m * G3HD;
            float ir = __ldcg(g0 + j), iz = __ldcg(g0 + HDEC_ + j), in = __ldcg(g0 + 2 * HDEC_ + j);
            float hr = 0.f, hz = 0.f, hn = 0.f;
#pragma unroll
            for (int s = 1; s < 6; s++) {
                const float* gp = g_dghp + (size_t)s * (B_ * G3HD) + (size_t)m * G3HD;
                hr += __ldcg(gp + j);
                hz += __ldcg(gp + HDEC_ + j);
                hn += __ldcg(gp + 2 * HDEC_ + j);
            }
            float rr = sigm(ir + hr);
            float zz = sigm(iz + hz);
            float nn = tanhf(in + rr * hn);
            float* hp = &g_hdec[(size_t)m * HDEC_ + j];
            float hv = __ldcg(hp);
            __stcg(hp, (1.f - zz) * nn + zz * hv);
        }
        gridbar();
        // D3: fc partials [B,512], K=640 (S=5)
#pragma unroll 1
        for (int tl = bid; tl < 4 * 8 * 5; tl += nblk) {
            int s = tl % 5, r = tl / 5;
            int n0 = (r % 8) * 64, m0 = (r / 8) * 32;
            float* C = g_fcp + (size_t)s * (B_ * FCN_);
            tile_gemm(&sm, g_hdec, HDEC_, 0, 1, 0, fc_W, HDEC_, fc_b, s == 0, C, FCN_, m0, n0, s * 128);
        }
        gridbar();
        // D4: out partials [B,128], K=512 (S=4); A = relu(sum5 fc partials)
#pragma unroll 1
        for (int tl = bid; tl < 4 * 2 * 4; tl += nblk) {
            int s = tl % 4, r = tl / 4;
            int n0 = (r % 2) * 64, m0 = (r / 2) * 32;
            float* C = g_outp + (size_t)s * (B_ * D_);
            tile_gemm(&sm, g_fcp, FCN_, (size_t)B_ * FCN_, 5, 2, out_W, FCN_, out_b, s == 0,
                      C, D_, m0, n0, s * 128);
        }
        gridbar();
        // D5: reduce -> x_mu[:, t, :] and feedback x_dec
        for (int i = gtid; i < B_ * D_; i += nthr) {
            int m = i / D_, d = i % D_;
            float v = 0.f;
#pragma unroll
            for (int s = 0; s < 4; s++) v += __ldcg(&g_outp[(size_t)s * B_ * D_ + m * D_ + d]);
            x_mu[((size_t)m * TL_ + t) * D_ + d] = v;
            __stcg(&g_xdec[m * D_ + d], v);
        }
        gridbar();
    }
}

// ---------------- host launch: single graph node ---------------------------
extern "C" void kernel_launch(void* const* d_in, const int* in_sizes, int n_in,
                              void* d_out, int out_size)
{
    (void)in_sizes; (void)n_in; (void)out_size;
    const float* past    = (const float*)d_in[0];
    const float* future  = (const float*)d_in[1];
    const float* eps     = (const float*)d_in[2];
    const float* phi_Wih = (const float*)d_in[3];
    const float* phi_Whh = (const float*)d_in[4];
    const float* phi_bih = (const float*)d_in[5];
    const float* phi_bhh = (const float*)d_in[6];
    const float* xr_Wih  = (const float*)d_in[7];
    const float* xr_Whh  = (const float*)d_in[8];
    const float* xr_bih  = (const float*)d_in[9];
    const float* xr_bhh  = (const float*)d_in[10];
    const float* mu_W1   = (const float*)d_in[11];
    const float* mu_b1   = (const float*)d_in[12];
    const float* mu_W2   = (const float*)d_in[13];
    const float* mu_b2   = (const float*)d_in[14];
    const float* mu_W3   = (const float*)d_in[15];
    const float* mu_b3   = (const float*)d_in[16];
    const float* lv_W1   = (const float*)d_in[17];
    const float* lv_b1   = (const float*)d_in[18];
    const float* lv_W2   = (const float*)d_in[19];
    const float* lv_b2   = (const float*)d_in[20];
    const float* lv_W3   = (const float*)d_in[21];
    const float* lv_b3   = (const float*)d_in[22];
    const float* dec_Wih = (const float*)d_in[23];
    const float* dec_Whh = (const float*)d_in[24];
    const float* dec_bih = (const float*)d_in[25];
    const float* dec_bhh = (const float*)d_in[26];
    const float* fc_W    = (const float*)d_in[27];
    const float* fc_b    = (const float*)d_in[28];
    const float* out_W   = (const float*)d_in[29];
    const float* out_b   = (const float*)d_in[30];

    float* outp = (float*)d_out;
    float* x_mu = outp;
    float* z_mu = outp + (size_t)B_ * TL_ * D_;
    float* z_lv = z_mu + (size_t)B_ * LD_;

    int dev = 0, sms = 148;
    cudaGetDevice(&dev);
    cudaDeviceGetAttribute(&sms, cudaDevAttrMultiProcessorCount, dev);
    int nblk = sms * 4;

    vae_persistent<<<nblk, 128>>>(
        past, future, eps,
        phi_Wih, phi_Whh, phi_bih, phi_bhh,
        xr_Wih, xr_Whh, xr_bih, xr_bhh,
        mu_W1, mu_b1, mu_W2, mu_b2, mu_W3, mu_b3,
        lv_W1, lv_b1, lv_W2, lv_b2, lv_W3, lv_b3,
        dec_Wih, dec_Whh, dec_bih, dec_bhh,
        fc_W, fc_b, out_W, out_b,
        x_mu, z_mu, z_lv);
}